// round 6
// baseline (speedup 1.0000x reference)
#include <cuda_runtime.h>
#include <cuda_bf16.h>

// InverseLeakySoftplus: solve a*x + (1-a)*softplus(x) = y, a = 0.1+0.4*sigmoid(raw_alpha).
//
// R5 finding: cubic-Hermite table (16B random LDS/elem, ~2.3x conflicts) put
// ~33us on the smem crossbar (128 B/cyc/SM), co-binding with the ~34us HBM
// floor (L1=81%, DRAM=48%). R6: LINEAR interp, float2 {x_k, dx_k} knots ->
// one LDS.64 = 8B/elem (~19us crossbar, below floor) -> HBM-bound.
// Accuracy: max|x''(y)| = max b*s(1-s)/(a+b*s)^3 ~= 7.2 @ a=0.138;
// h=0.01 -> lerp err <= 7.2*h^2/8 ~= 9e-5 abs (~2e-5 rel; threshold 1e-3).
// Outside [-16,16] (inputs N(0,3)): x=y (err ~1e-7) / x=y/a (exact).

#define NSEG  3200
#define YMINF (-16.0f)
#define H_F   0.01f
#define INVH  100.0f
#define TOFF  1600.0f          // -YMIN/h
#define TPB   256
#define IPT   4                // float4 per thread

__device__ float2 g_tab[NSEG];  // {x_k, x_{k+1}-x_k}
__device__ float  g_inva;

// ---------- table builder ----------
__device__ __forceinline__ float solve_knot(float y, float a, float oma, float inva)
{
    float x = (y > 0.0f) ? y : y * inva;
#pragma unroll
    for (int it = 0; it < 7; ++it) {             // <=1e-7 abs (R2 analysis)
        float e  = __expf(-fabsf(x));
        float op = 1.0f + e;
        float sp = __logf(op) + fmaxf(x, 0.0f);
        float fx = fmaf(a, x, oma * sp);
        float num = (x >= 0.0f) ? fmaf(a, e, 1.0f) : (a + e);
        x -= __fdividef((fx - y) * op, num);
    }
    return x;
}

__global__ void build_table(const float* __restrict__ raw_alpha)
{
    int k = blockIdx.x * blockDim.x + threadIdx.x;
    float r    = __ldg(raw_alpha);
    float sig  = __fdividef(1.0f, 1.0f + __expf(-r));
    float a    = fmaf(0.4f, sig, 0.1f);
    float oma  = 1.0f - a;
    float inva = __fdividef(1.0f, a);
    if (k == 0) g_inva = inva;
    if (k < NSEG) {
        float y0 = YMINF + (float)k * H_F;
        float x0 = solve_knot(y0, a, oma, inva);
        float x1 = solve_knot(y0 + H_F, a, oma, inva);
        g_tab[k] = make_float2(x0, x1 - x0);
    }
}

// ---------- main: lerp, one LDS.64 per element, zero MUFU ----------
__device__ __forceinline__ float lerp_solve(float y, float inva,
                                            const float2* __restrict__ s_tab)
{
    float t = fmaf(y, INVH, TOFF);
    t = fminf(fmaxf(t, 0.0f), (float)NSEG - 0.001f);
    int   k  = (int)t;
    float fr = t - (float)k;
    float2 p = s_tab[k];
    float x  = fmaf(fr, p.y, p.x);
    x = (y >=  16.0f) ? y        : x;
    x = (y <= -16.0f) ? y * inva : x;
    return x;
}

__global__ void inv_lsp_main(const float4* __restrict__ in,
                             float4* __restrict__ out, int n4)
{
    __shared__ float2 s_tab[NSEG];
    for (int j = threadIdx.x; j < NSEG; j += TPB) s_tab[j] = g_tab[j];
    float inva = g_inva;
    __syncthreads();

    int base = blockIdx.x * (TPB * IPT) + threadIdx.x;
    float4 v[IPT];
    int    ok[IPT];
#pragma unroll
    for (int j = 0; j < IPT; ++j) {              // front-batch loads (MLP)
        int i = base + j * TPB;
        ok[j] = (i < n4);
        if (ok[j]) v[j] = in[i];
    }
#pragma unroll
    for (int j = 0; j < IPT; ++j) {
        if (ok[j]) {
            float4 rr;
            rr.x = lerp_solve(v[j].x, inva, s_tab);
            rr.y = lerp_solve(v[j].y, inva, s_tab);
            rr.z = lerp_solve(v[j].z, inva, s_tab);
            rr.w = lerp_solve(v[j].w, inva, s_tab);
            out[base + j * TPB] = rr;
        }
    }
}

// ---------- scalar tail (safety; unused when n % 4 == 0) ----------
__global__ void inv_lsp_scalar_tail(const float* __restrict__ in,
                                    float* __restrict__ out,
                                    int start, int n)
{
    int i = start + blockIdx.x * blockDim.x + threadIdx.x;
    if (i >= n) return;
    float inva = g_inva;
    float a    = __fdividef(1.0f, inva);
    float oma  = 1.0f - a;
    float y = in[i];
    float x = (y > 0.0f) ? y : y * inva;
#pragma unroll
    for (int it = 0; it < 8; ++it) {
        float e  = __expf(-fabsf(x));
        float op = 1.0f + e;
        float sp = __logf(op) + fmaxf(x, 0.0f);
        float fx = fmaf(a, x, oma * sp);
        float num = (x >= 0.0f) ? fmaf(a, e, 1.0f) : (a + e);
        x -= __fdividef((fx - y) * op, num);
    }
    out[i] = x;
}

extern "C" void kernel_launch(void* const* d_in, const int* in_sizes, int n_in,
                              void* d_out, int out_size)
{
    const float* in        = (const float*)d_in[0];
    const float* raw_alpha = (const float*)d_in[1];
    float* out             = (float*)d_out;
    int n = in_sizes[0];

    build_table<<<(NSEG + 127) / 128, 128>>>(raw_alpha);

    int n4 = n / 4;
    if (n4 > 0) {
        int per_block = TPB * IPT;
        int blocks = (n4 + per_block - 1) / per_block;
        inv_lsp_main<<<blocks, TPB>>>((const float4*)in, (float4*)out, n4);
    }
    int rem = n - n4 * 4;
    if (rem > 0) {
        inv_lsp_scalar_tail<<<1, 256>>>(in, out, n4 * 4, n);
    }
}

// round 7
// speedup vs baseline: 1.4234x; 1.4234x over previous
#include <cuda_runtime.h>
#include <cuda_bf16.h>

// InverseLeakySoftplus: solve a*x + (1-a)*softplus(x) = y, a = 0.1+0.4*sigmoid(raw_alpha).
//
// R6 post-mortem: the 25.6KB smem table was copied by ALL 8192 blocks ->
// 210MB of L2 traffic (~17us) + per-block serialized prologue (issue=32%).
// R7: persistent grid (608 blocks = 152 SMs x 4, grid-stride) -> copy traffic
// 15.6MB (~1us), prologue amortized over ~14 iterations. Main path unchanged:
// linear interp, one LDS.64/elem, zero MUFU. Expect HBM-bound (~40us).
// Accuracy: h=0.01 -> lerp err <= 7.2*h^2/8 ~= 9e-5 abs (measured rel 1.2e-6).

#define NSEG  3200
#define YMINF (-16.0f)
#define H_F   0.01f
#define INVH  100.0f
#define TOFF  1600.0f          // -YMIN/h
#define TPB   256
#define IPT   4                // float4 per thread per grid-stride step
#define NBLOCKS 608            // 152 SMs x 4 blocks (32 warps/SM)

__device__ float2 g_tab[NSEG];  // {x_k, x_{k+1}-x_k}
__device__ float  g_inva;

// ---------- table builder ----------
__device__ __forceinline__ float solve_knot(float y, float a, float oma, float inva)
{
    float x = (y > 0.0f) ? y : y * inva;
#pragma unroll
    for (int it = 0; it < 7; ++it) {
        float e  = __expf(-fabsf(x));
        float op = 1.0f + e;
        float sp = __logf(op) + fmaxf(x, 0.0f);
        float fx = fmaf(a, x, oma * sp);
        float num = (x >= 0.0f) ? fmaf(a, e, 1.0f) : (a + e);
        x -= __fdividef((fx - y) * op, num);
    }
    return x;
}

__global__ void build_table(const float* __restrict__ raw_alpha)
{
    int k = blockIdx.x * blockDim.x + threadIdx.x;
    float r    = __ldg(raw_alpha);
    float sig  = __fdividef(1.0f, 1.0f + __expf(-r));
    float a    = fmaf(0.4f, sig, 0.1f);
    float oma  = 1.0f - a;
    float inva = __fdividef(1.0f, a);
    if (k == 0) g_inva = inva;
    if (k < NSEG) {
        float y0 = YMINF + (float)k * H_F;
        float x0 = solve_knot(y0, a, oma, inva);
        float x1 = solve_knot(y0 + H_F, a, oma, inva);
        g_tab[k] = make_float2(x0, x1 - x0);
    }
}

// ---------- main: lerp, one LDS.64 per element, zero MUFU ----------
__device__ __forceinline__ float lerp_solve(float y, float inva,
                                            const float2* __restrict__ s_tab)
{
    float t = fmaf(y, INVH, TOFF);
    t = fminf(fmaxf(t, 0.0f), (float)NSEG - 0.001f);
    int   k  = (int)t;
    float fr = t - (float)k;
    float2 p = s_tab[k];
    float x  = fmaf(fr, p.y, p.x);
    x = (y >=  16.0f) ? y        : x;
    x = (y <= -16.0f) ? y * inva : x;
    return x;
}

__global__ void __launch_bounds__(TPB, 4)
inv_lsp_main(const float4* __restrict__ in, float4* __restrict__ out, int n4)
{
    __shared__ float2 s_tab[NSEG];
    for (int j = threadIdx.x; j < NSEG; j += TPB) s_tab[j] = g_tab[j];
    float inva = g_inva;
    __syncthreads();

    int tid     = blockIdx.x * TPB + threadIdx.x;
    int gstride = gridDim.x * TPB;
    long long step = (long long)gstride * IPT;

    for (long long i0 = tid; i0 < n4; i0 += step) {
        float4 v[IPT];
        int    ok[IPT];
#pragma unroll
        for (int j = 0; j < IPT; ++j) {          // front-batched loads (MLP=4)
            long long i = i0 + (long long)j * gstride;
            ok[j] = (i < n4);
            if (ok[j]) v[j] = in[i];
        }
#pragma unroll
        for (int j = 0; j < IPT; ++j) {
            if (ok[j]) {
                float4 rr;
                rr.x = lerp_solve(v[j].x, inva, s_tab);
                rr.y = lerp_solve(v[j].y, inva, s_tab);
                rr.z = lerp_solve(v[j].z, inva, s_tab);
                rr.w = lerp_solve(v[j].w, inva, s_tab);
                out[i0 + (long long)j * gstride] = rr;
            }
        }
    }
}

// ---------- scalar tail (safety; unused when n % 4 == 0) ----------
__global__ void inv_lsp_scalar_tail(const float* __restrict__ in,
                                    float* __restrict__ out,
                                    int start, int n)
{
    int i = start + blockIdx.x * blockDim.x + threadIdx.x;
    if (i >= n) return;
    float inva = g_inva;
    float a    = __fdividef(1.0f, inva);
    float oma  = 1.0f - a;
    float y = in[i];
    float x = (y > 0.0f) ? y : y * inva;
#pragma unroll
    for (int it = 0; it < 8; ++it) {
        float e  = __expf(-fabsf(x));
        float op = 1.0f + e;
        float sp = __logf(op) + fmaxf(x, 0.0f);
        float fx = fmaf(a, x, oma * sp);
        float num = (x >= 0.0f) ? fmaf(a, e, 1.0f) : (a + e);
        x -= __fdividef((fx - y) * op, num);
    }
    out[i] = x;
}

extern "C" void kernel_launch(void* const* d_in, const int* in_sizes, int n_in,
                              void* d_out, int out_size)
{
    const float* in        = (const float*)d_in[0];
    const float* raw_alpha = (const float*)d_in[1];
    float* out             = (float*)d_out;
    int n = in_sizes[0];

    build_table<<<(NSEG + 127) / 128, 128>>>(raw_alpha);

    int n4 = n / 4;
    if (n4 > 0) {
        int blocks = NBLOCKS;
        int needed = (n4 + TPB - 1) / TPB;
        if (needed < blocks) blocks = needed;
        inv_lsp_main<<<blocks, TPB>>>((const float4*)in, (float4*)out, n4);
    }
    int rem = n - n4 * 4;
    if (rem > 0) {
        inv_lsp_scalar_tail<<<1, 256>>>(in, out, n4 * 4, n);
    }
}